// round 17
// baseline (speedup 1.0000x reference)
#include <cuda_runtime.h>
#include <math_constants.h>

#define BS          32
#define NUM_GT      64
#define NUM_PRIORS  8400
#define NUM_CLASSES 80
#define TOPK        9

// output layout (float32, concat of returned tuple)
#define OFF_L 0
#define OFF_B (BS*NUM_PRIORS)                       // 268800
#define OFF_S (OFF_B + BS*NUM_PRIORS*4)             // 1344000
#define OFF_F (OFF_S + BS*NUM_PRIORS*NUM_CLASSES)   // 22848000

typedef unsigned long long u64;

#define SPLIT 4
#define PPB   (NUM_PRIORS/SPLIT)   // 2100 priors per block
#define FT    1024                 // threads per block

// analytic prior cell box from per-batch prior index
__device__ __forceinline__ float4 cell_box(int p) {
  int l = (p < 6400) ? 0 : (p < 8000 ? 1 : 2);
  int n = (l == 0) ? 80 : (l == 1 ? 40 : 20);
  float s = (l == 0) ? 8.f : (l == 1 ? 16.f : 32.f);
  int st = (l == 0) ? 0 : (l == 1 ? 6400 : 8000);
  int rel = p - st;
  int jy = rel / n, jx = rel - jy*n;
  float px = ((float)jx + 0.5f)*s, py = ((float)jy + 0.5f)*s;
  float h = 2.5f*s;
  return make_float4(px - h, py - h, px + h, py + h);
}

__device__ __forceinline__ float cell_iou(float4 T, float4 cb, float pa) {
  float iw = fmaxf(fminf(T.z, cb.z) - fmaxf(T.x, cb.x), 0.f);
  float ih = fmaxf(fminf(T.w, cb.w) - fmaxf(T.y, cb.y), 0.f);
  float inter = iw*ih;
  float ga = (T.z - T.x)*(T.w - T.y);
  return inter / fmaxf(ga + pa - inter, 1e-6f);
}

// Fused single kernel. Block = (batch, split of 2100 priors).
// Phase A: all 32 warps run the 5x5-window ATSS select for ALL 64 gts of the
//          batch (redundant across splits; math identical to the 2-kernel
//          version) and scatter claims FILTERED to this block's prior range
//          into a private smem claims array (exact same claim set).
// Phase B: R8 k_out body over the block's 2100 priors, claims + gt tables in
//          smem, warp-shuffle score-slab streaming stores.
__global__ __launch_bounds__(FT) void k_fused(
    const float4* __restrict__ gt_bboxes,
    const int*    __restrict__ gt_labels,
    const float*  __restrict__ pad_flag,
    const float4* __restrict__ pred,
    float* __restrict__ out)
{
  __shared__ u64    cl  [PPB];     // 16800 B  per-block claims
  __shared__ float4 sgt [NUM_GT];  // 1024 B
  __shared__ int    slab[NUM_GT];  // 256 B

  const int b     = blockIdx.x >> 2;
  const int split = blockIdx.x & 3;
  const int p0    = split * PPB;
  const int tid   = threadIdx.x;
  const int lane  = tid & 31;
  const int w     = tid >> 5;      // warp 0..31

  // ---- phase 0: zero claims, stage gt tables ----
  for (int i = tid; i < PPB; i += FT) cl[i] = 0;
  if (tid < NUM_GT) {
    sgt [tid] = __ldg(&gt_bboxes[b*NUM_GT + tid]);
    slab[tid] = __ldg(&gt_labels[b*NUM_GT + tid]);
  }
  __syncthreads();

  // ---- phase A: select (warp w handles gts 2w and 2w+1) ----
  {
    const int  qy  = lane / 5;              // 0..6 (lanes 25..31 invalid)
    const int  dxi = lane - qy*5 - 2;       // -2..2
    const int  dyi = qy - 2;
    const bool lane_ok = lane < 25;

    const int   Cn [3] = {80, 40, 20};
    const float Cs [3] = {8.f, 16.f, 32.f};
    const float Cis[3] = {0.125f, 0.0625f, 0.03125f};
    const int   Cst[3] = {0, 6400, 8000};

    for (int gg = 0; gg < 2; gg++) {
      const int g = (w << 1) + gg;
      const float4 G = sgt[g];
      const float gcx = (G.x + G.z)*0.5f, gcy = (G.y + G.w)*0.5f;
      const float garea = (G.z - G.x)*(G.w - G.y);

      float ov[3]; bool win[3]; float pxv[3], pyv[3]; int pidxv[3];
      float osum = 0.f;

      #pragma unroll
      for (int l = 0; l < 3; l++) {
        const int n = Cn[l]; const float s = Cs[l];
        const int jx0 = (int)floorf(gcx * Cis[l]);   // exact (pow2 scale)
        const int jy0 = (int)floorf(gcy * Cis[l]);
        const int jx = jx0 + dxi, jy = jy0 + dyi;
        const bool v = lane_ok && (unsigned)jx < (unsigned)n && (unsigned)jy < (unsigned)n;

        const float px = ((float)jx + 0.5f) * s;     // == reference center, exact
        const float py = ((float)jy + 0.5f) * s;
        const float dx = gcx - px, dy = gcy - py;
        const float d  = fmaf(dx, dx, dy*dy);
        const int   pidx = Cst[l] + jy*n + jx;
        const u64 key = v ? (((u64)__float_as_uint(d) << 32) | (unsigned)pidx) : ~0ull;

        // rank = #keys strictly less (keys unique among valid lanes)
        int r = 0;
        #pragma unroll
        for (int src = 0; src < 25; src++) {
          u64 a = __shfl_sync(0xffffffffu, key, src);
          r += (a < key);
        }
        const bool ww = v && (r < TOPK);   // exactly 9 winners per level
        win[l] = ww; pxv[l] = px; pyv[l] = py; pidxv[l] = pidx;

        float o = 0.f;
        if (ww) {
          const float h = 2.5f*s;
          const float x1 = px - h, x2 = px + h, y1 = py - h, y2 = py + h;
          float iw = fmaxf(fminf(G.z, x2) - fmaxf(G.x, x1), 0.f);
          float ih = fmaxf(fminf(G.w, y2) - fmaxf(G.y, y1), 0.f);
          float inter = iw*ih;
          float pa = (x2 - x1)*(y2 - y1);
          o = inter / fmaxf(garea + pa - inter, 1e-6f);
        }
        ov[l] = o;
        osum += o;
      }

      // thr = mean + std(ddof=1) over the 27 winner overlaps
      float ssum = osum;
      #pragma unroll
      for (int off = 16; off; off >>= 1) ssum += __shfl_xor_sync(0xffffffffu, ssum, off);
      const float mean = ssum / 27.f;
      float vsum = 0.f;
      #pragma unroll
      for (int l = 0; l < 3; l++)
        if (win[l]) { float e = ov[l] - mean; vsum = fmaf(e, e, vsum); }
      #pragma unroll
      for (int off = 16; off; off >>= 1) vsum += __shfl_xor_sync(0xffffffffu, vsum, off);
      const float thr = mean + sqrtf(vsum / 26.f);

      const bool pad = __ldg(&pad_flag[b*NUM_GT + g]) > 0.f;
      #pragma unroll
      for (int l = 0; l < 3; l++) {
        if (win[l] && pad && ov[l] > thr) {
          float mm = fminf(fminf(pxv[l] - G.x, pyv[l] - G.y),
                           fminf(G.z - pxv[l], G.w - pyv[l]));
          if (mm > 1e-9f) {   // prior center strictly inside gt
            int rel = pidxv[l] - p0;
            if ((unsigned)rel < (unsigned)PPB)   // filter to this block's range
              atomicOr(&cl[rel], 1ull << g);
          }
        }
      }
    }
  }
  __syncthreads();

  // ---- phase B: resolve + stores (R8 k_out body, claims/gt in smem) ----
  #pragma unroll
  for (int it = 0; it < (PPB + FT - 1)/FT; it++) {   // 3 iterations
    const int  i   = it*FT + tid;
    const bool on  = i < PPB;
    const int  key = b*NUM_PRIORS + p0 + i;

    u64 m = on ? cl[i] : 0;
    const int fg = __popcll(m);
    int gi = (fg >= 1) ? (__ffsll((long long)m) - 1) : 0;

    // warp-cooperative first-max argmax over ALL 64 gts for fg>1 lanes
    unsigned need = __ballot_sync(0xffffffffu, fg > 1);
    while (need) {
      const int leader = __ffs(need) - 1; need &= need - 1;
      const int li = (i & ~31) | leader;            // leader's in-block index
      const float4 cb = cell_box(p0 + li);
      const float  pa = (cb.z - cb.x)*(cb.w - cb.y);
      // lane evaluates gt=lane and gt=lane+32 (lower index wins ties)
      float o0 = cell_iou(sgt[lane],      cb, pa);
      float o1 = cell_iou(sgt[lane + 32], cb, pa);
      float bv = o0; int bi = lane;
      if (o1 > bv) { bv = o1; bi = lane + 32; }
      #pragma unroll
      for (int off = 16; off; off >>= 1) {
        float ovx = __shfl_xor_sync(0xffffffffu, bv, off);
        int   oix = __shfl_xor_sync(0xffffffffu, bi, off);
        if (ovx > bv || (ovx == bv && oix < bi)) { bv = ovx; bi = oix; }
      }
      if (lane == leader) gi = bi;
    }

    const float4 T = sgt[gi];
    float labelv, fgm; int col = -1; float val = 0.f;
    if (fg > 0) {
      int lab = slab[gi];
      labelv = (float)lab; col = lab; fgm = 1.f;
      // score weight = IoU(gt, pred), union + 1e-9
      float4 P = __ldg(&pred[key]);
      float iw = fmaxf(fminf(T.z, P.z) - fmaxf(T.x, P.x), 0.f);
      float ih = fmaxf(fminf(T.w, P.w) - fmaxf(T.y, P.y), 0.f);
      float inter = iw*ih;
      float ga = (T.z - T.x)*(T.w - T.y);
      float pa = (P.z - P.x)*(P.w - P.y);
      val = inter / (ga + pa - inter + 1e-9f);
    } else {
      labelv = (float)NUM_CLASSES; fgm = 0.f;   // background; bbox = gt[b][0]
    }

    if (on) {
      __stcs(&out[OFF_L + key], labelv);
      __stcs((float4*)out + (OFF_B >> 2) + key, T);
      __stcs(&out[OFF_F + key], fgm);
    }

    // score tile: warp's (up to) 32 contiguous priors => vc*20 float4s
    const int pw = it*FT + (tid & ~31);      // tile's first in-block index
    const int vc = min(32, PPB - pw);
    if (vc > 0) {
      const int fc = vc * (NUM_CLASSES/4);
      float4* sco = (float4*)out + (OFF_S >> 2)
                  + (size_t)(b*NUM_PRIORS + p0 + pw)*(NUM_CLASSES/4);
      for (int j = lane; j < fc; j += 32) {
        const int lp = j / 20;
        const int c0 = (j - lp*20) * 4;
        const int   cll = __shfl_sync(0xffffffffu, col, lp);
        const float vv  = __shfl_sync(0xffffffffu, val, lp);
        float4 rr;
        rr.x = (cll == c0    ) ? vv : 0.f;
        rr.y = (cll == c0 + 1) ? vv : 0.f;
        rr.z = (cll == c0 + 2) ? vv : 0.f;
        rr.w = (cll == c0 + 3) ? vv : 0.f;
        __stcs(&sco[j], rr);
      }
    }
  }
}

extern "C" void kernel_launch(void* const* d_in, const int* in_sizes, int n_in,
                              void* d_out, int out_size)
{
  const float4* pred = (const float4*)d_in[0];
  const int*    gtl  = (const int*)d_in[2];
  const float4* gtb  = (const float4*)d_in[3];
  const float*  pad  = (const float*)d_in[4];
  float* out = (float*)d_out;

  k_fused<<<BS*SPLIT, FT>>>(gtb, gtl, pad, pred, out);
}